// round 1
// baseline (speedup 1.0000x reference)
#include <cuda_runtime.h>
#include <cstdint>

// Problem constants
#define BB 2
#define LL 2048
#define EE 512
#define KH 4
#define KE 256

// ---------------- scratch (device globals; no allocation allowed) ----------
__device__ float g_xq [(size_t)BB*LL*KH*KE];     // (B,L,K*KE) 16MB
__device__ float g_xkb[(size_t)BB*LL*KH*KE];     // 16MB
__device__ float g_qn [(size_t)BB*LL*KH];
__device__ float g_kn [(size_t)BB*LL*KH];
__device__ float g_H  [(size_t)BB*KH*LL*LL];     // 134MB, softmax in-place -> P
__device__ float g_Vp [(size_t)BB*KH*LL*EE];     // 33.5MB

// ---------------- generic tiled SGEMM, stage-specialized --------------------
// STAGE 0: xq  = xsa @ Wq^T                    (M=4096,N=1024,K=512, NT)
// STAGE 1: xkb = xsa @ Wk^T + biasW            (same, NT)
// STAGE 2: H   = (2*xq.xkb^T - qn - kn)/16     (z=8: M=N=2048,K=256, NT)
// STAGE 3: Vp  = xsa @ Wv3[k]                  (z=8: M=2048,N=512,K=512, NN)
// STAGE 4: out = P @ Vp + bias2                (z=8: M=2048,N=512,K=2048, NN)

#define BM 128
#define BN 128
#define BKK 16
#define TM 8
#define TN 8

template<int STAGE>
__global__ __launch_bounds__(256, 2)
void gemm_k(const float* __restrict__ Ab, const float* __restrict__ Bb,
            float* __restrict__ Cb,
            const float* __restrict__ aux1, const float* __restrict__ aux2)
{
    constexpr bool NT  = (STAGE <= 2);
    constexpr int  Kd  = (STAGE <= 1) ? 512  : (STAGE == 2 ? 256  : (STAGE == 3 ? 512 : 2048));
    constexpr int  lda = (STAGE <= 1) ? 512  : (STAGE == 2 ? 1024 : (STAGE == 3 ? 512 : 2048));
    constexpr int  ldb = (STAGE <= 1) ? 512  : (STAGE == 2 ? 1024 : 512);
    constexpr int  ldc = (STAGE <= 1) ? 1024 : (STAGE == 2 ? 2048 : (STAGE == 3 ? 512 : 2048));

    const int z = blockIdx.z;
    const int b = z >> 2, k = z & 3;

    const float* A = Ab;
    const float* Bm = Bb;
    float* C = Cb;
    if (STAGE == 2) {
        size_t o = (size_t)b * LL * (KH*KE) + (size_t)k * KE;
        A += o; Bm += o;
        C += (size_t)z * LL * LL;
    } else if (STAGE == 3) {
        A  += (size_t)b * LL * EE;
        Bm += (size_t)k * EE * EE;
        C  += (size_t)z * LL * EE;
    } else if (STAGE == 4) {
        A  += (size_t)z * LL * LL;
        Bm += (size_t)z * LL * EE;
        C  += (size_t)b * LL * (KH*EE) + (size_t)k * EE;
    }

    __shared__ float As[BKK][BM + 4];
    __shared__ float Bs[BKK][BN + 4];

    const int tid = threadIdx.x;
    const int tx = tid & 15;       // -> N
    const int ty = tid >> 4;       // -> M
    const int rowBlk = blockIdx.y * BM;
    const int colBlk = blockIdx.x * BN;

    float acc[TM][TN];
    #pragma unroll
    for (int i = 0; i < TM; i++)
        #pragma unroll
        for (int j = 0; j < TN; j++) acc[i][j] = 0.f;

    for (int kt = 0; kt < Kd; kt += BKK) {
        // ---- load A tile (BM x BKK), transpose into As[k][m]
        {
            const float* Ag = A + (size_t)rowBlk * lda + kt;
            #pragma unroll
            for (int i = 0; i < 2; i++) {
                int s  = tid + i * 256;
                int r  = s >> 2;
                int c4 = s & 3;
                float4 v = *reinterpret_cast<const float4*>(Ag + (size_t)r * lda + c4 * 4);
                As[c4*4+0][r] = v.x; As[c4*4+1][r] = v.y;
                As[c4*4+2][r] = v.z; As[c4*4+3][r] = v.w;
            }
        }
        // ---- load B tile
        if (NT) {
            const float* Bg = Bm + (size_t)colBlk * ldb + kt;
            #pragma unroll
            for (int i = 0; i < 2; i++) {
                int s  = tid + i * 256;
                int r  = s >> 2;
                int c4 = s & 3;
                float4 v = *reinterpret_cast<const float4*>(Bg + (size_t)r * ldb + c4 * 4);
                Bs[c4*4+0][r] = v.x; Bs[c4*4+1][r] = v.y;
                Bs[c4*4+2][r] = v.z; Bs[c4*4+3][r] = v.w;
            }
        } else {
            const float* Bg = Bm + (size_t)kt * ldb + colBlk;
            #pragma unroll
            for (int i = 0; i < 2; i++) {
                int s  = tid + i * 256;
                int kk = s >> 5;
                int n4 = s & 31;
                float4 v = *reinterpret_cast<const float4*>(Bg + (size_t)kk * ldb + n4 * 4);
                *reinterpret_cast<float4*>(&Bs[kk][n4 * 4]) = v;
            }
        }
        __syncthreads();

        #pragma unroll
        for (int kk = 0; kk < BKK; kk++) {
            float a[TM], bv[TN];
            #pragma unroll
            for (int i = 0; i < TM; i += 4)
                *reinterpret_cast<float4*>(&a[i]) =
                    *reinterpret_cast<const float4*>(&As[kk][ty * TM + i]);
            #pragma unroll
            for (int j = 0; j < TN; j += 4)
                *reinterpret_cast<float4*>(&bv[j]) =
                    *reinterpret_cast<const float4*>(&Bs[kk][tx * TN + j]);
            #pragma unroll
            for (int i = 0; i < TM; i++)
                #pragma unroll
                for (int j = 0; j < TN; j++)
                    acc[i][j] += a[i] * bv[j];
        }
        __syncthreads();
    }

    // ---- epilogue + store
    #pragma unroll
    for (int i = 0; i < TM; i++) {
        const int gi = rowBlk + ty * TM + i;
        #pragma unroll
        for (int j = 0; j < TN; j += 4) {
            const int gj = colBlk + tx * TN + j;
            float4 v;
            v.x = acc[i][j]; v.y = acc[i][j+1]; v.z = acc[i][j+2]; v.w = acc[i][j+3];
            if (STAGE == 1) {
                // +biasW: col c = k*256+d -> biasW[d*4 + k]
                v.x += aux1[((gj+0) & 255) * 4 + ((gj+0) >> 8)];
                v.y += aux1[((gj+1) & 255) * 4 + ((gj+1) >> 8)];
                v.z += aux1[((gj+2) & 255) * 4 + ((gj+2) >> 8)];
                v.w += aux1[((gj+3) & 255) * 4 + ((gj+3) >> 8)];
            } else if (STAGE == 2) {
                const float qi = aux1[(size_t)(b * LL + gi) * 4 + k];
                v.x = (2.f * v.x - qi - aux2[(size_t)(b * LL + gj+0) * 4 + k]) * 0.0625f;
                v.y = (2.f * v.y - qi - aux2[(size_t)(b * LL + gj+1) * 4 + k]) * 0.0625f;
                v.z = (2.f * v.z - qi - aux2[(size_t)(b * LL + gj+2) * 4 + k]) * 0.0625f;
                v.w = (2.f * v.w - qi - aux2[(size_t)(b * LL + gj+3) * 4 + k]) * 0.0625f;
            } else if (STAGE == 4) {
                // +bias2: local col f -> bias2W[f*4 + k]
                v.x += aux1[(gj+0) * 4 + k];
                v.y += aux1[(gj+1) * 4 + k];
                v.z += aux1[(gj+2) * 4 + k];
                v.w += aux1[(gj+3) * 4 + k];
            }
            *reinterpret_cast<float4*>(C + (size_t)gi * ldc + gj) = v;
        }
    }
}

// ---------------- row norms: qn/kn per (b,l,k) ------------------------------
__global__ void norms_k(const float* __restrict__ xq, const float* __restrict__ xkb,
                        float* __restrict__ qn, float* __restrict__ kn)
{
    const int row  = blockIdx.x;            // b*L + l  (0..4095)
    const int w    = threadIdx.x >> 5;      // head
    const int lane = threadIdx.x & 31;
    const size_t base = (size_t)row * (KH*KE) + (size_t)w * KE + lane * 8;

    float4 a0 = *reinterpret_cast<const float4*>(xq + base);
    float4 a1 = *reinterpret_cast<const float4*>(xq + base + 4);
    float sq = a0.x*a0.x + a0.y*a0.y + a0.z*a0.z + a0.w*a0.w
             + a1.x*a1.x + a1.y*a1.y + a1.z*a1.z + a1.w*a1.w;

    float4 b0 = *reinterpret_cast<const float4*>(xkb + base);
    float4 b1 = *reinterpret_cast<const float4*>(xkb + base + 4);
    float sk = b0.x*b0.x + b0.y*b0.y + b0.z*b0.z + b0.w*b0.w
             + b1.x*b1.x + b1.y*b1.y + b1.z*b1.z + b1.w*b1.w;

    #pragma unroll
    for (int o = 16; o; o >>= 1) {
        sq += __shfl_xor_sync(0xFFFFFFFFu, sq, o);
        sk += __shfl_xor_sync(0xFFFFFFFFu, sk, o);
    }
    if (lane == 0) {
        qn[(size_t)row * 4 + w] = sq;
        kn[(size_t)row * 4 + w] = sk;
    }
}

// ---------------- in-place row softmax (rows of length 2048) ----------------
__global__ __launch_bounds__(256)
void softmax_k(float* __restrict__ H)
{
    const int row = blockIdx.x;
    float* p = H + (size_t)row * 2048;
    const int tid  = threadIdx.x;
    const int lane = tid & 31, warp = tid >> 5;

    float x[8];
    float4 v0 = *reinterpret_cast<const float4*>(p + tid * 8);
    float4 v1 = *reinterpret_cast<const float4*>(p + tid * 8 + 4);
    x[0]=v0.x; x[1]=v0.y; x[2]=v0.z; x[3]=v0.w;
    x[4]=v1.x; x[5]=v1.y; x[6]=v1.z; x[7]=v1.w;

    float m = x[0];
    #pragma unroll
    for (int i = 1; i < 8; i++) m = fmaxf(m, x[i]);
    #pragma unroll
    for (int o = 16; o; o >>= 1) m = fmaxf(m, __shfl_xor_sync(0xFFFFFFFFu, m, o));

    __shared__ float sm[8];
    __shared__ float ss[8];
    if (lane == 0) sm[warp] = m;
    __syncthreads();
    float M = sm[0];
    #pragma unroll
    for (int i = 1; i < 8; i++) M = fmaxf(M, sm[i]);

    float s = 0.f;
    #pragma unroll
    for (int i = 0; i < 8; i++) { x[i] = __expf(x[i] - M); s += x[i]; }
    #pragma unroll
    for (int o = 16; o; o >>= 1) s += __shfl_xor_sync(0xFFFFFFFFu, s, o);
    if (lane == 0) ss[warp] = s;
    __syncthreads();
    float S = 0.f;
    #pragma unroll
    for (int i = 0; i < 8; i++) S += ss[i];
    const float inv = 1.f / S;

    v0.x = x[0]*inv; v0.y = x[1]*inv; v0.z = x[2]*inv; v0.w = x[3]*inv;
    v1.x = x[4]*inv; v1.y = x[5]*inv; v1.z = x[6]*inv; v1.w = x[7]*inv;
    *reinterpret_cast<float4*>(p + tid * 8)     = v0;
    *reinterpret_cast<float4*>(p + tid * 8 + 4) = v1;
}

// ---------------- launch ----------------------------------------------------
extern "C" void kernel_launch(void* const* d_in, const int* in_sizes, int n_in,
                              void* d_out, int out_size)
{
    const float* xsa    = (const float*)d_in[0];   // (B,L,E)
    const float* Wq     = (const float*)d_in[1];   // (K*KE, E)
    const float* Wk     = (const float*)d_in[2];   // (K*KE, E)
    const float* Wv     = (const float*)d_in[3];   // (E, K*E)
    const float* biasW  = (const float*)d_in[4];   // (KE, K)
    const float* bias2W = (const float*)d_in[5];   // (E, K)
    float* out = (float*)d_out;                    // (B,L,K*E)

    float *p_xq, *p_xkb, *p_qn, *p_kn, *p_H, *p_Vp;
    cudaGetSymbolAddress((void**)&p_xq,  g_xq);
    cudaGetSymbolAddress((void**)&p_xkb, g_xkb);
    cudaGetSymbolAddress((void**)&p_qn,  g_qn);
    cudaGetSymbolAddress((void**)&p_kn,  g_kn);
    cudaGetSymbolAddress((void**)&p_H,   g_H);
    cudaGetSymbolAddress((void**)&p_Vp,  g_Vp);

    // S0: xq = xsa @ Wq^T
    gemm_k<0><<<dim3(1024/BN, 4096/BM, 1), 256>>>(xsa, Wq, p_xq, nullptr, nullptr);
    // S1: xkb = xsa @ Wk^T + biasW
    gemm_k<1><<<dim3(1024/BN, 4096/BM, 1), 256>>>(xsa, Wk, p_xkb, biasW, nullptr);
    // norms
    norms_k<<<BB*LL, 128>>>(p_xq, p_xkb, p_qn, p_kn);
    // S2: H scores
    gemm_k<2><<<dim3(2048/BN, 2048/BM, BB*KH), 256>>>(p_xq, p_xkb, p_H, p_qn, p_kn);
    // softmax in place
    softmax_k<<<BB*KH*LL, 256>>>(p_H);
    // S3: Vp = xsa @ Wv3[k]
    gemm_k<3><<<dim3(512/BN, 2048/BM, BB*KH), 256>>>(xsa, Wv, p_Vp, nullptr, nullptr);
    // S4: out = P @ Vp + bias2
    gemm_k<4><<<dim3(512/BN, 2048/BM, BB*KH), 256>>>(p_H, p_Vp, out, bias2W, nullptr);
}

// round 4
// speedup vs baseline: 2.3748x; 2.3748x over previous
#include <cuda_runtime.h>
#include <cuda_bf16.h>
#include <cstdint>

#define BB 2
#define LL 2048
#define EE 512
#define KH 4
#define KE 256
typedef __nv_bfloat16 bf16;
typedef __nv_bfloat162 bf162;

// ---------------- scratch (device globals) ----------------------------------
__device__ float g_xq [(size_t)4096*1024];
__device__ float g_xkb[(size_t)4096*1024];
__device__ float g_qn [4096*4];
__device__ float g_kn [4096*4];
__device__ float g_H  [(size_t)8*2048*2048];

__device__ bf16 g_xsa_h[(size_t)4096*512],  g_xsa_l[(size_t)4096*512];
__device__ bf16 g_wq_h [(size_t)1024*512],  g_wq_l [(size_t)1024*512];
__device__ bf16 g_wk_h [(size_t)1024*512],  g_wk_l [(size_t)1024*512];
__device__ bf16 g_wv_h [(size_t)512*2048],  g_wv_l [(size_t)512*2048];
__device__ bf16 g_xq_h [(size_t)4096*1024], g_xq_l [(size_t)4096*1024];
__device__ bf16 g_xkb_h[(size_t)4096*1024], g_xkb_l[(size_t)4096*1024];
__device__ bf16 g_P_h  [(size_t)8*2048*2048], g_P_l[(size_t)8*2048*2048];
__device__ bf16 g_vp_h [(size_t)8*2048*512],  g_vp_l[(size_t)8*2048*512];

// ---------------- helpers ----------------------------------------------------
__device__ __forceinline__ uint32_t smem_u32(const void* p) {
    uint32_t a;
    asm("{ .reg .u64 t; cvta.to.shared.u64 t, %1; cvt.u32.u64 %0, t; }" : "=r"(a) : "l"(p));
    return a;
}
__device__ __forceinline__ void cpa16(uint32_t d, const void* s) {
    asm volatile("cp.async.cg.shared.global [%0], [%1], 16;" :: "r"(d), "l"(s));
}
#define CP_COMMIT() asm volatile("cp.async.commit_group;" ::: "memory")
#define CP_WAIT1()  asm volatile("cp.async.wait_group 1;" ::: "memory")

__device__ __forceinline__ void ldsm_x4(uint32_t& r0, uint32_t& r1, uint32_t& r2,
                                        uint32_t& r3, uint32_t a) {
    asm volatile("ldmatrix.sync.aligned.m8n8.x4.shared.b16 {%0,%1,%2,%3}, [%4];"
                 : "=r"(r0), "=r"(r1), "=r"(r2), "=r"(r3) : "r"(a));
}
__device__ __forceinline__ void ldsm_x4t(uint32_t& r0, uint32_t& r1, uint32_t& r2,
                                         uint32_t& r3, uint32_t a) {
    asm volatile("ldmatrix.sync.aligned.m8n8.x4.trans.shared.b16 {%0,%1,%2,%3}, [%4];"
                 : "=r"(r0), "=r"(r1), "=r"(r2), "=r"(r3) : "r"(a));
}
__device__ __forceinline__ void mma16816(float c[4], const uint32_t a[4],
                                         const uint32_t bq[2]) {
    asm volatile("mma.sync.aligned.m16n8k16.row.col.f32.bf16.bf16.f32 "
                 "{%0,%1,%2,%3}, {%4,%5,%6,%7}, {%8,%9}, {%0,%1,%2,%3};"
                 : "+f"(c[0]), "+f"(c[1]), "+f"(c[2]), "+f"(c[3])
                 : "r"(a[0]), "r"(a[1]), "r"(a[2]), "r"(a[3]), "r"(bq[0]), "r"(bq[1]));
}
__device__ __forceinline__ void split2(float a, float b, bf162& h, bf162& l) {
    h = __floats2bfloat162_rn(a, b);
    l = __floats2bfloat162_rn(a - __bfloat162float(h.x), b - __bfloat162float(h.y));
}

// ---------------- GEMM: C[M][N] = A[M][K] * B^T (B stored per-stage) ---------
// NT stages (0,1,2): B gmem is [n][k] row-major (K contiguous).
// NN stages (3,4):   B gmem is [k][n] row-major (N contiguous), ldmatrix.trans.
// Stage 3 B = Wv.reshape(4,512,512)[k] = flat chunk k*262144, ld=512.
// All inputs are split bf16 hi/lo; accumulate Ah*Bh + Ah*Bl + Al*Bh in fp32.

template<int STAGE>
__global__ __launch_bounds__(256, 2)
void hgemm(const bf16* __restrict__ gAh, const bf16* __restrict__ gAl,
           const bf16* __restrict__ gBh, const bf16* __restrict__ gBl,
           float* __restrict__ Cf, bf16* __restrict__ Ch, bf16* __restrict__ Cl,
           const float* __restrict__ aux1, const float* __restrict__ aux2)
{
    constexpr bool NT  = (STAGE <= 2);
    constexpr int  Kd  = (STAGE <= 1) ? 512  : (STAGE == 2 ? 256  : (STAGE == 3 ? 512 : 2048));
    constexpr int  ldA = (STAGE <= 1) ? 512  : (STAGE == 2 ? 1024 : (STAGE == 3 ? 512 : 2048));
    constexpr int  ldB = (STAGE <= 1) ? 512  : (STAGE == 2 ? 1024 : 512);
    constexpr int  ldC = (STAGE <= 1) ? 1024 : (STAGE == 2 ? 2048 : (STAGE == 3 ? 512 : 2048));
    constexpr int  NC  = Kd / 32;

    extern __shared__ char smem[];
    const uint32_t sb = smem_u32(smem);
    const int tid = threadIdx.x;
    const int z = blockIdx.z, b = z >> 2, k = z & 3;

    const bf16 *Ah = gAh, *Al = gAl, *Bh = gBh, *Bl = gBl;
    size_t coff = 0;
    if (STAGE == 2) {
        size_t o = (size_t)(b * 2048) * 1024 + (size_t)k * 256;
        Ah += o; Al += o; Bh += o; Bl += o;
        coff = (size_t)z * 2048 * 2048;
    } else if (STAGE == 3) {
        size_t oa = (size_t)(b * 2048) * 512;
        Ah += oa; Al += oa;
        size_t ob = (size_t)k * 512 * 512;          // flat reshape chunk (FIX)
        Bh += ob; Bl += ob;
        coff = (size_t)z * 2048 * 512;
    } else if (STAGE == 4) {
        size_t oa = (size_t)z * 2048 * 2048;
        Ah += oa; Al += oa;
        size_t ob = (size_t)z * 2048 * 512;
        Bh += ob; Bl += ob;
        coff = (size_t)(b * 2048) * 2048 + (size_t)k * 512;
    }
    const int yBlk = blockIdx.y * 128, xBlk = blockIdx.x * 128;
    Ah += (size_t)yBlk * ldA; Al += (size_t)yBlk * ldA;
    if (NT) { Bh += (size_t)xBlk * ldB; Bl += (size_t)xBlk * ldB; }
    else    { Bh += xBlk; Bl += xBlk; }
    if (Cf) Cf += coff;
    if (Ch) { Ch += coff; Cl += coff; }

    const int wid = tid >> 5, lane = tid & 31;
    const int m0 = (wid & 3) * 32, n0 = (wid >> 2) * 64;

    float acc[2][8][4];
    #pragma unroll
    for (int am = 0; am < 2; am++)
        #pragma unroll
        for (int j = 0; j < 8; j++)
            #pragma unroll
            for (int q = 0; q < 4; q++) acc[am][j][q] = 0.f;

    auto load_chunk = [&](int c, int buf) {
        uint32_t s0 = sb + buf * 32768;
        #pragma unroll
        for (int h = 0; h < 2; h++) {
            int s = tid + h * 256;
            int r = s >> 2, q = s & 3;
            uint32_t d = s0 + r * 64 + ((q ^ ((r >> 1) & 3)) << 4);
            cpa16(d,        Ah + (size_t)r * ldA + c * 32 + q * 8);
            cpa16(d + 8192, Al + (size_t)r * ldA + c * 32 + q * 8);
        }
        if (NT) {
            #pragma unroll
            for (int h = 0; h < 2; h++) {
                int s = tid + h * 256;
                int r = s >> 2, q = s & 3;
                uint32_t d = s0 + 16384 + r * 64 + ((q ^ ((r >> 1) & 3)) << 4);
                cpa16(d,        Bh + (size_t)r * ldB + c * 32 + q * 8);
                cpa16(d + 8192, Bl + (size_t)r * ldB + c * 32 + q * 8);
            }
        } else {
            #pragma unroll
            for (int h = 0; h < 2; h++) {
                int s = tid + h * 256;
                int kk = s >> 4, q = s & 15;
                uint32_t d = s0 + 16384 + kk * 256 + ((q ^ (kk & 7)) << 4);
                cpa16(d,        Bh + (size_t)(c * 32 + kk) * ldB + q * 8);
                cpa16(d + 8192, Bl + (size_t)(c * 32 + kk) * ldB + q * 8);
            }
        }
    };

    load_chunk(0, 0);
    CP_COMMIT();

    #pragma unroll 1
    for (int c = 0; c < NC; c++) {
        if (c + 1 < NC) load_chunk(c + 1, (c + 1) & 1);
        CP_COMMIT();
        CP_WAIT1();
        __syncthreads();

        const uint32_t s0 = sb + (c & 1) * 32768;
        #pragma unroll
        for (int p = 0; p < 3; p++) {
            const uint32_t sA = s0 + (p == 2 ? 8192 : 0);
            const uint32_t sB = s0 + 16384 + (p == 1 ? 8192 : 0);
            #pragma unroll
            for (int s = 0; s < 2; s++) {
                uint32_t a[2][4];
                #pragma unroll
                for (int am = 0; am < 2; am++) {
                    int row = m0 + am * 16 + (lane & 15);
                    int q = s * 2 + (lane >> 4);
                    uint32_t addr = sA + row * 64 + ((q ^ ((row >> 1) & 3)) << 4);
                    ldsm_x4(a[am][0], a[am][1], a[am][2], a[am][3], addr);
                }
                uint32_t bq[8][2];
                if (NT) {
                    #pragma unroll
                    for (int bn = 0; bn < 4; bn++) {
                        int row = n0 + bn * 16 + (lane & 15);
                        int q = s * 2 + (lane >> 4);
                        uint32_t addr = sB + row * 64 + ((q ^ ((row >> 1) & 3)) << 4);
                        uint32_t r0, r1, r2, r3;
                        ldsm_x4(r0, r1, r2, r3, addr);
                        bq[2*bn][0] = r0; bq[2*bn][1] = r2;
                        bq[2*bn+1][0] = r1; bq[2*bn+1][1] = r3;
                    }
                } else {
                    #pragma unroll
                    for (int bn = 0; bn < 4; bn++) {
                        int g = lane >> 3;
                        int kk = s * 16 + (g & 1) * 8 + (lane & 7);
                        int q = (n0 + bn * 16) / 8 + (g >> 1);
                        uint32_t addr = sB + kk * 256 + ((q ^ (kk & 7)) << 4);
                        uint32_t r0, r1, r2, r3;
                        ldsm_x4t(r0, r1, r2, r3, addr);
                        bq[2*bn][0] = r0; bq[2*bn][1] = r1;
                        bq[2*bn+1][0] = r2; bq[2*bn+1][1] = r3;
                    }
                }
                #pragma unroll
                for (int am = 0; am < 2; am++)
                    #pragma unroll
                    for (int j = 0; j < 8; j++)
                        mma16816(acc[am][j], a[am], bq[j]);
            }
        }
        __syncthreads();
    }

    // ---- epilogue ----
    #pragma unroll
    for (int am = 0; am < 2; am++) {
        const int gi0 = yBlk + m0 + am * 16 + (lane >> 2);
        #pragma unroll
        for (int j = 0; j < 8; j++) {
            const int gj = xBlk + n0 + j * 8 + (lane & 3) * 2;
            #pragma unroll
            for (int half = 0; half < 2; half++) {
                const int gi = gi0 + half * 8;
                float v0 = acc[am][j][half * 2 + 0];
                float v1 = acc[am][j][half * 2 + 1];
                if (STAGE == 1) {
                    v0 += aux1[((gj + 0) & 255) * 4 + ((gj + 0) >> 8)];
                    v1 += aux1[((gj + 1) & 255) * 4 + ((gj + 1) >> 8)];
                } else if (STAGE == 2) {
                    const float qi = aux1[(size_t)(b * 2048 + gi) * 4 + k];
                    v0 = (2.f * v0 - qi - aux2[(size_t)(b * 2048 + gj + 0) * 4 + k]) * 0.0625f;
                    v1 = (2.f * v1 - qi - aux2[(size_t)(b * 2048 + gj + 1) * 4 + k]) * 0.0625f;
                } else if (STAGE == 4) {
                    v0 += aux1[(gj + 0) * 4 + k];
                    v1 += aux1[(gj + 1) * 4 + k];
                }
                const size_t idx = (size_t)gi * ldC + gj;
                if (STAGE != 3)
                    *reinterpret_cast<float2*>(Cf + idx) = make_float2(v0, v1);
                if (STAGE <= 1 || STAGE == 3) {
                    bf162 h, l;
                    split2(v0, v1, h, l);
                    *reinterpret_cast<bf162*>(Ch + idx) = h;
                    *reinterpret_cast<bf162*>(Cl + idx) = l;
                }
            }
        }
    }
}

// ---------------- fp32 -> bf16 hi/lo split -----------------------------------
__global__ void split_k(const float4* __restrict__ src, bf162* __restrict__ hi,
                        bf162* __restrict__ lo, int n4)
{
    int i = blockIdx.x * 256 + threadIdx.x;
    if (i >= n4) return;
    float4 v = src[i];
    bf162 h0, l0, h1, l1;
    split2(v.x, v.y, h0, l0);
    split2(v.z, v.w, h1, l1);
    hi[2 * i] = h0; hi[2 * i + 1] = h1;
    lo[2 * i] = l0; lo[2 * i + 1] = l1;
}

// ---------------- row norms --------------------------------------------------
__global__ void norms_k(const float* __restrict__ xq, const float* __restrict__ xkb,
                        float* __restrict__ qn, float* __restrict__ kn)
{
    const int row  = blockIdx.x;
    const int w    = threadIdx.x >> 5;
    const int lane = threadIdx.x & 31;
    const size_t base = (size_t)row * 1024 + (size_t)w * 256 + lane * 8;

    float4 a0 = *reinterpret_cast<const float4*>(xq + base);
    float4 a1 = *reinterpret_cast<const float4*>(xq + base + 4);
    float sq = a0.x*a0.x + a0.y*a0.y + a0.z*a0.z + a0.w*a0.w
             + a1.x*a1.x + a1.y*a1.y + a1.z*a1.z + a1.w*a1.w;
    float4 b0 = *reinterpret_cast<const float4*>(xkb + base);
    float4 b1 = *reinterpret_cast<const float4*>(xkb + base + 4);
    float sk = b0.x*b0.x + b0.y*b0.y + b0.z*b0.z + b0.w*b0.w
             + b1.x*b1.x + b1.y*b1.y + b1.z*b1.z + b1.w*b1.w;

    #pragma unroll
    for (int o = 16; o; o >>= 1) {
        sq += __shfl_xor_sync(0xFFFFFFFFu, sq, o);
        sk += __shfl_xor_sync(0xFFFFFFFFu, sk, o);
    }
    if (lane == 0) {
        qn[(size_t)row * 4 + w] = sq;
        kn[(size_t)row * 4 + w] = sk;
    }
}

// ---------------- softmax: read H f32, write P hi/lo bf16 --------------------
__global__ __launch_bounds__(256)
void softmax_k(const float* __restrict__ H, bf16* __restrict__ Ph, bf16* __restrict__ Pl)
{
    const int row = blockIdx.x;
    const float* p = H + (size_t)row * 2048;
    const int tid  = threadIdx.x;
    const int lane = tid & 31, warp = tid >> 5;

    float x[8];
    float4 v0 = *reinterpret_cast<const float4*>(p + tid * 8);
    float4 v1 = *reinterpret_cast<const float4*>(p + tid * 8 + 4);
    x[0]=v0.x; x[1]=v0.y; x[2]=v0.z; x[3]=v0.w;
    x[4]=v1.x; x[5]=v1.y; x[6]=v1.z; x[7]=v1.w;

    float m = x[0];
    #pragma unroll
    for (int i = 1; i < 8; i++) m = fmaxf(m, x[i]);
    #pragma unroll
    for (int o = 16; o; o >>= 1) m = fmaxf(m, __shfl_xor_sync(0xFFFFFFFFu, m, o));

    __shared__ float sm[8];
    __shared__ float ss[8];
    if (lane == 0) sm[warp] = m;
    __syncthreads();
    float M = sm[0];
    #pragma unroll
    for (int i = 1; i < 8; i++) M = fmaxf(M, sm[i]);

    float s = 0.f;
    #pragma unroll
    for (int i = 0; i < 8; i++) { x[i] = __expf(x[i] - M); s += x[i]; }
    #pragma unroll
    for (int o = 16; o; o >>= 1) s += __shfl_xor_sync(0xFFFFFFFFu, s, o);
    if (lane == 0) ss[warp] = s;
    __syncthreads();
    float S = 0.f;
    #pragma unroll
    for (int i = 0; i < 8; i++) S += ss[i];
    const float inv = 1.f / S;

    bf162* ph = reinterpret_cast<bf162*>(Ph + (size_t)row * 2048 + tid * 8);
    bf162* pl = reinterpret_cast<bf162*>(Pl + (size_t)row * 2048 + tid * 8);
    #pragma unroll
    for (int i = 0; i < 4; i++) {
        bf162 h, l;
        split2(x[2*i] * inv, x[2*i+1] * inv, h, l);
        ph[i] = h; pl[i] = l;
    }
}

// ---------------- launch ------------------------------------------------------
extern "C" void kernel_launch(void* const* d_in, const int* in_sizes, int n_in,
                              void* d_out, int out_size)
{
    const float* xsa    = (const float*)d_in[0];
    const float* Wq     = (const float*)d_in[1];
    const float* Wk     = (const float*)d_in[2];
    const float* Wv     = (const float*)d_in[3];
    const float* biasW  = (const float*)d_in[4];
    const float* bias2W = (const float*)d_in[5];
    float* out = (float*)d_out;

    float *p_xq, *p_xkb, *p_qn, *p_kn, *p_H;
    bf16 *xsa_h, *xsa_l, *wq_h, *wq_l, *wk_h, *wk_l, *wv_h, *wv_l;
    bf16 *xq_h, *xq_l, *xkb_h, *xkb_l, *P_h, *P_l, *vp_h, *vp_l;
    cudaGetSymbolAddress((void**)&p_xq,  g_xq);
    cudaGetSymbolAddress((void**)&p_xkb, g_xkb);
    cudaGetSymbolAddress((void**)&p_qn,  g_qn);
    cudaGetSymbolAddress((void**)&p_kn,  g_kn);
    cudaGetSymbolAddress((void**)&p_H,   g_H);
    cudaGetSymbolAddress((void**)&xsa_h, g_xsa_h);
    cudaGetSymbolAddress((void**)&xsa_l, g_xsa_l);
    cudaGetSymbolAddress((void**)&wq_h,  g_wq_h);
    cudaGetSymbolAddress((void**)&wq_l,  g_wq_l);
    cudaGetSymbolAddress((void**)&wk_h,  g_wk_h);
    cudaGetSymbolAddress((void**)&wk_l,  g_wk_l);
    cudaGetSymbolAddress((void**)&wv_h,  g_wv_h);
    cudaGetSymbolAddress((void**)&wv_l,  g_wv_l);
    cudaGetSymbolAddress((void**)&xq_h,  g_xq_h);
    cudaGetSymbolAddress((void**)&xq_l,  g_xq_l);
    cudaGetSymbolAddress((void**)&xkb_h, g_xkb_h);
    cudaGetSymbolAddress((void**)&xkb_l, g_xkb_l);
    cudaGetSymbolAddress((void**)&P_h,   g_P_h);
    cudaGetSymbolAddress((void**)&P_l,   g_P_l);
    cudaGetSymbolAddress((void**)&vp_h,  g_vp_h);
    cudaGetSymbolAddress((void**)&vp_l,  g_vp_l);

    cudaFuncSetAttribute(hgemm<0>, cudaFuncAttributeMaxDynamicSharedMemorySize, 65536);
    cudaFuncSetAttribute(hgemm<1>, cudaFuncAttributeMaxDynamicSharedMemorySize, 65536);
    cudaFuncSetAttribute(hgemm<2>, cudaFuncAttributeMaxDynamicSharedMemorySize, 65536);
    cudaFuncSetAttribute(hgemm<3>, cudaFuncAttributeMaxDynamicSharedMemorySize, 65536);
    cudaFuncSetAttribute(hgemm<4>, cudaFuncAttributeMaxDynamicSharedMemorySize, 65536);

    // input splits
    split_k<<<2048, 256>>>((const float4*)xsa, (bf162*)xsa_h, (bf162*)xsa_l, 524288);
    split_k<<<512,  256>>>((const float4*)Wq,  (bf162*)wq_h,  (bf162*)wq_l,  131072);
    split_k<<<512,  256>>>((const float4*)Wk,  (bf162*)wk_h,  (bf162*)wk_l,  131072);
    split_k<<<1024, 256>>>((const float4*)Wv,  (bf162*)wv_h,  (bf162*)wv_l,  262144);

    // S0: xq = xsa @ Wq^T  (f32 + hi/lo)
    hgemm<0><<<dim3(8, 32, 1), 256, 65536>>>(xsa_h, xsa_l, wq_h, wq_l,
                                             p_xq, xq_h, xq_l, nullptr, nullptr);
    // S1: xkb = xsa @ Wk^T + biasW
    hgemm<1><<<dim3(8, 32, 1), 256, 65536>>>(xsa_h, xsa_l, wk_h, wk_l,
                                             p_xkb, xkb_h, xkb_l, biasW, nullptr);
    // norms
    norms_k<<<4096, 128>>>(p_xq, p_xkb, p_qn, p_kn);
    // S2: H = (2*xq.xkb^T - qn - kn)/16
    hgemm<2><<<dim3(16, 16, 8), 256, 65536>>>(xq_h, xq_l, xkb_h, xkb_l,
                                              p_H, nullptr, nullptr, p_qn, p_kn);
    // softmax -> P hi/lo
    softmax_k<<<8 * 2048, 256>>>(p_H, P_h, P_l);
    // S3: Vp = xsa @ Wv3[k]  (hi/lo only)
    hgemm<3><<<dim3(4, 16, 8), 256, 65536>>>(xsa_h, xsa_l, wv_h, wv_l,
                                             nullptr, vp_h, vp_l, nullptr, nullptr);
    // S4: out = P @ Vp + bias2
    hgemm<4><<<dim3(4, 16, 8), 256, 65536>>>(P_h, P_l, vp_h, vp_l,
                                             out, nullptr, nullptr, bias2W, nullptr);
}

// round 5
// speedup vs baseline: 2.5526x; 1.0749x over previous
#include <cuda_runtime.h>
#include <cuda_bf16.h>
#include <cstdint>

#define BB 2
#define LL 2048
#define EE 512
#define KH 4
#define KE 256
typedef __nv_bfloat16 bf16;
typedef __nv_bfloat162 bf162;

// ---------------- scratch (device globals) ----------------------------------
__device__ float g_xq [(size_t)4096*1024];
__device__ float g_xkb[(size_t)4096*1024];
__device__ float g_qn [4096*4];
__device__ float g_kn [4096*4];
__device__ float g_H  [(size_t)8*2048*2048];

__device__ bf16 g_xsa_h[(size_t)4096*512],  g_xsa_l[(size_t)4096*512];
__device__ bf16 g_wq_h [(size_t)1024*512],  g_wq_l [(size_t)1024*512];
__device__ bf16 g_wk_h [(size_t)1024*512],  g_wk_l [(size_t)1024*512];
__device__ bf16 g_wv_h [(size_t)512*2048],  g_wv_l [(size_t)512*2048];
__device__ bf16 g_xq_h [(size_t)4096*1024], g_xq_l [(size_t)4096*1024];
__device__ bf16 g_xkb_h[(size_t)4096*1024], g_xkb_l[(size_t)4096*1024];
__device__ bf16 g_P_h  [(size_t)8*2048*2048], g_P_l[(size_t)8*2048*2048];
__device__ bf16 g_vp_h [(size_t)8*2048*512],  g_vp_l[(size_t)8*2048*512];

// ---------------- helpers ----------------------------------------------------
__device__ __forceinline__ uint32_t smem_u32(const void* p) {
    uint32_t a;
    asm("{ .reg .u64 t; cvta.to.shared.u64 t, %1; cvt.u32.u64 %0, t; }" : "=r"(a) : "l"(p));
    return a;
}
__device__ __forceinline__ void cpa16(uint32_t d, const void* s) {
    asm volatile("cp.async.cg.shared.global [%0], [%1], 16;" :: "r"(d), "l"(s));
}
#define CP_COMMIT() asm volatile("cp.async.commit_group;" ::: "memory")
#define CP_WAIT1()  asm volatile("cp.async.wait_group 1;" ::: "memory")

__device__ __forceinline__ void ldsm_x4(uint32_t& r0, uint32_t& r1, uint32_t& r2,
                                        uint32_t& r3, uint32_t a) {
    asm volatile("ldmatrix.sync.aligned.m8n8.x4.shared.b16 {%0,%1,%2,%3}, [%4];"
                 : "=r"(r0), "=r"(r1), "=r"(r2), "=r"(r3) : "r"(a));
}
__device__ __forceinline__ void ldsm_x4t(uint32_t& r0, uint32_t& r1, uint32_t& r2,
                                         uint32_t& r3, uint32_t a) {
    asm volatile("ldmatrix.sync.aligned.m8n8.x4.trans.shared.b16 {%0,%1,%2,%3}, [%4];"
                 : "=r"(r0), "=r"(r1), "=r"(r2), "=r"(r3) : "r"(a));
}
__device__ __forceinline__ void mma16816(float c[4], const uint32_t a[4],
                                         const uint32_t bq[2]) {
    asm volatile("mma.sync.aligned.m16n8k16.row.col.f32.bf16.bf16.f32 "
                 "{%0,%1,%2,%3}, {%4,%5,%6,%7}, {%8,%9}, {%0,%1,%2,%3};"
                 : "+f"(c[0]), "+f"(c[1]), "+f"(c[2]), "+f"(c[3])
                 : "r"(a[0]), "r"(a[1]), "r"(a[2]), "r"(a[3]), "r"(bq[0]), "r"(bq[1]));
}
__device__ __forceinline__ void split2(float a, float b, bf162& h, bf162& l) {
    h = __floats2bfloat162_rn(a, b);
    l = __floats2bfloat162_rn(a - __bfloat162float(h.x), b - __bfloat162float(h.y));
}

// ---------------- GEMM: C[M][N] = A[M][K] * B^T (B stored per-stage) ---------
// NT stages (0,1,2): B gmem is [n][k] row-major (K contiguous).
// NN stages (3,4):   B gmem is [k][n] row-major (N contiguous), ldmatrix.trans.
// Stage 3 B = Wv.reshape(4,512,512)[k] = flat chunk k*262144, ld=512.
// Split bf16 hi/lo; accumulate Ah*Bh + Ah*Bl + Al*Bh in fp32.
// 3-stage cp.async pipeline (3 x 32KB buffers), fragment-reuse inner loop.

template<int STAGE>
__global__ __launch_bounds__(256, 2)
void hgemm(const bf16* __restrict__ gAh, const bf16* __restrict__ gAl,
           const bf16* __restrict__ gBh, const bf16* __restrict__ gBl,
           float* __restrict__ Cf, bf16* __restrict__ Ch, bf16* __restrict__ Cl,
           const float* __restrict__ aux1, const float* __restrict__ aux2)
{
    constexpr bool NT  = (STAGE <= 2);
    constexpr int  Kd  = (STAGE <= 1) ? 512  : (STAGE == 2 ? 256  : (STAGE == 3 ? 512 : 2048));
    constexpr int  ldA = (STAGE <= 1) ? 512  : (STAGE == 2 ? 1024 : (STAGE == 3 ? 512 : 2048));
    constexpr int  ldB = (STAGE <= 1) ? 512  : (STAGE == 2 ? 1024 : 512);
    constexpr int  ldC = (STAGE <= 1) ? 1024 : (STAGE == 2 ? 2048 : (STAGE == 3 ? 512 : 2048));
    constexpr int  NC  = Kd / 32;

    extern __shared__ char smem[];
    const uint32_t sb = smem_u32(smem);
    const int tid = threadIdx.x;
    const int z = blockIdx.z, b = z >> 2, k = z & 3;

    const bf16 *Ah = gAh, *Al = gAl, *Bh = gBh, *Bl = gBl;
    size_t coff = 0;
    if (STAGE == 2) {
        size_t o = (size_t)(b * 2048) * 1024 + (size_t)k * 256;
        Ah += o; Al += o; Bh += o; Bl += o;
        coff = (size_t)z * 2048 * 2048;
    } else if (STAGE == 3) {
        size_t oa = (size_t)(b * 2048) * 512;
        Ah += oa; Al += oa;
        size_t ob = (size_t)k * 512 * 512;          // flat reshape chunk
        Bh += ob; Bl += ob;
        coff = (size_t)z * 2048 * 512;
    } else if (STAGE == 4) {
        size_t oa = (size_t)z * 2048 * 2048;
        Ah += oa; Al += oa;
        size_t ob = (size_t)z * 2048 * 512;
        Bh += ob; Bl += ob;
        coff = (size_t)(b * 2048) * 2048 + (size_t)k * 512;
    }
    const int yBlk = blockIdx.y * 128, xBlk = blockIdx.x * 128;
    Ah += (size_t)yBlk * ldA; Al += (size_t)yBlk * ldA;
    if (NT) { Bh += (size_t)xBlk * ldB; Bl += (size_t)xBlk * ldB; }
    else    { Bh += xBlk; Bl += xBlk; }
    if (Cf) Cf += coff;
    if (Ch) { Ch += coff; Cl += coff; }

    const int wid = tid >> 5, lane = tid & 31;
    const int m0 = (wid & 3) * 32, n0 = (wid >> 2) * 64;

    float acc[2][8][4];
    #pragma unroll
    for (int am = 0; am < 2; am++)
        #pragma unroll
        for (int j = 0; j < 8; j++)
            #pragma unroll
            for (int q = 0; q < 4; q++) acc[am][j][q] = 0.f;

    auto load_chunk = [&](int c, int buf) {
        uint32_t s0 = sb + buf * 32768;
        #pragma unroll
        for (int h = 0; h < 2; h++) {
            int s = tid + h * 256;
            int r = s >> 2, q = s & 3;
            uint32_t d = s0 + r * 64 + ((q ^ ((r >> 1) & 3)) << 4);
            cpa16(d,        Ah + (size_t)r * ldA + c * 32 + q * 8);
            cpa16(d + 8192, Al + (size_t)r * ldA + c * 32 + q * 8);
        }
        if (NT) {
            #pragma unroll
            for (int h = 0; h < 2; h++) {
                int s = tid + h * 256;
                int r = s >> 2, q = s & 3;
                uint32_t d = s0 + 16384 + r * 64 + ((q ^ ((r >> 1) & 3)) << 4);
                cpa16(d,        Bh + (size_t)r * ldB + c * 32 + q * 8);
                cpa16(d + 8192, Bl + (size_t)r * ldB + c * 32 + q * 8);
            }
        } else {
            #pragma unroll
            for (int h = 0; h < 2; h++) {
                int s = tid + h * 256;
                int kk = s >> 4, q = s & 15;
                uint32_t d = s0 + 16384 + kk * 256 + ((q ^ (kk & 7)) << 4);
                cpa16(d,        Bh + (size_t)(c * 32 + kk) * ldB + q * 8);
                cpa16(d + 8192, Bl + (size_t)(c * 32 + kk) * ldB + q * 8);
            }
        }
    };

    // prologue: chunks 0 and 1 in flight
    load_chunk(0, 0); CP_COMMIT();
    load_chunk(1, 1); CP_COMMIT();

    #pragma unroll 1
    for (int c = 0; c < NC; c++) {
        CP_WAIT1();            // chunk c resident (newest pending = c+1)
        __syncthreads();       // all warps done with chunk c-1 (buffer (c+2)%3)
        if (c + 2 < NC) load_chunk(c + 2, (c + 2) % 3);
        CP_COMMIT();           // one group per iteration keeps wait bookkeeping exact

        const uint32_t s0 = sb + (c % 3) * 32768;
        #pragma unroll
        for (int s = 0; s < 2; s++) {
            // ---- unique A fragments (hi & lo) once per k-step ----
            uint32_t ah[2][4], al[2][4];
            #pragma unroll
            for (int am = 0; am < 2; am++) {
                int row = m0 + am * 16 + (lane & 15);
                int q = s * 2 + (lane >> 4);
                uint32_t addr = s0 + row * 64 + ((q ^ ((row >> 1) & 3)) << 4);
                ldsm_x4(ah[am][0], ah[am][1], ah[am][2], ah[am][3], addr);
                ldsm_x4(al[am][0], al[am][1], al[am][2], al[am][3], addr + 8192);
            }
            // ---- B in pairs of 16-col groups: 4 j-values per pass ----
            #pragma unroll
            for (int bp = 0; bp < 2; bp++) {
                uint32_t bh[4][2], bl[4][2];
                if (NT) {
                    #pragma unroll
                    for (int i = 0; i < 2; i++) {
                        int bn = 2 * bp + i;
                        int row = n0 + bn * 16 + (lane & 15);
                        int q = s * 2 + (lane >> 4);
                        uint32_t addr = s0 + 16384 + row * 64 + ((q ^ ((row >> 1) & 3)) << 4);
                        uint32_t r0, r1, r2, r3;
                        ldsm_x4(r0, r1, r2, r3, addr);
                        bh[2*i][0] = r0; bh[2*i][1] = r2;
                        bh[2*i+1][0] = r1; bh[2*i+1][1] = r3;
                        ldsm_x4(r0, r1, r2, r3, addr + 8192);
                        bl[2*i][0] = r0; bl[2*i][1] = r2;
                        bl[2*i+1][0] = r1; bl[2*i+1][1] = r3;
                    }
                } else {
                    #pragma unroll
                    for (int i = 0; i < 2; i++) {
                        int bn = 2 * bp + i;
                        int g = lane >> 3;
                        int kk = s * 16 + (g & 1) * 8 + (lane & 7);
                        int q = (n0 + bn * 16) / 8 + (g >> 1);
                        uint32_t addr = s0 + 16384 + kk * 256 + ((q ^ (kk & 7)) << 4);
                        uint32_t r0, r1, r2, r3;
                        ldsm_x4t(r0, r1, r2, r3, addr);
                        bh[2*i][0] = r0; bh[2*i][1] = r1;
                        bh[2*i+1][0] = r2; bh[2*i+1][1] = r3;
                        ldsm_x4t(r0, r1, r2, r3, addr + 8192);
                        bl[2*i][0] = r0; bl[2*i][1] = r1;
                        bl[2*i+1][0] = r2; bl[2*i+1][1] = r3;
                    }
                }
                // 3 products, 8 independent accumulator chains per product
                #pragma unroll
                for (int am = 0; am < 2; am++)
                    #pragma unroll
                    for (int jj = 0; jj < 4; jj++)
                        mma16816(acc[am][4*bp+jj], ah[am], bh[jj]);
                #pragma unroll
                for (int am = 0; am < 2; am++)
                    #pragma unroll
                    for (int jj = 0; jj < 4; jj++)
                        mma16816(acc[am][4*bp+jj], ah[am], bl[jj]);
                #pragma unroll
                for (int am = 0; am < 2; am++)
                    #pragma unroll
                    for (int jj = 0; jj < 4; jj++)
                        mma16816(acc[am][4*bp+jj], al[am], bh[jj]);
            }
        }
    }

    // ---- epilogue ----
    #pragma unroll
    for (int am = 0; am < 2; am++) {
        const int gi0 = yBlk + m0 + am * 16 + (lane >> 2);
        #pragma unroll
        for (int j = 0; j < 8; j++) {
            const int gj = xBlk + n0 + j * 8 + (lane & 3) * 2;
            #pragma unroll
            for (int half = 0; half < 2; half++) {
                const int gi = gi0 + half * 8;
                float v0 = acc[am][j][half * 2 + 0];
                float v1 = acc[am][j][half * 2 + 1];
                if (STAGE == 1) {
                    v0 += aux1[((gj + 0) & 255) * 4 + ((gj + 0) >> 8)];
                    v1 += aux1[((gj + 1) & 255) * 4 + ((gj + 1) >> 8)];
                } else if (STAGE == 2) {
                    const float qi = aux1[(size_t)(b * 2048 + gi) * 4 + k];
                    v0 = (2.f * v0 - qi - aux2[(size_t)(b * 2048 + gj + 0) * 4 + k]) * 0.0625f;
                    v1 = (2.f * v1 - qi - aux2[(size_t)(b * 2048 + gj + 1) * 4 + k]) * 0.0625f;
                } else if (STAGE == 4) {
                    v0 += aux1[(gj + 0) * 4 + k];
                    v1 += aux1[(gj + 1) * 4 + k];
                }
                const size_t idx = (size_t)gi * ldC + gj;
                if (STAGE != 3)
                    *reinterpret_cast<float2*>(Cf + idx) = make_float2(v0, v1);
                if (STAGE <= 1 || STAGE == 3) {
                    bf162 h, l;
                    split2(v0, v1, h, l);
                    *reinterpret_cast<bf162*>(Ch + idx) = h;
                    *reinterpret_cast<bf162*>(Cl + idx) = l;
                }
            }
        }
    }
}

// ---------------- fp32 -> bf16 hi/lo split -----------------------------------
__global__ void split_k(const float4* __restrict__ src, bf162* __restrict__ hi,
                        bf162* __restrict__ lo, int n4)
{
    int i = blockIdx.x * 256 + threadIdx.x;
    if (i >= n4) return;
    float4 v = src[i];
    bf162 h0, l0, h1, l1;
    split2(v.x, v.y, h0, l0);
    split2(v.z, v.w, h1, l1);
    hi[2 * i] = h0; hi[2 * i + 1] = h1;
    lo[2 * i] = l0; lo[2 * i + 1] = l1;
}

// ---------------- row norms --------------------------------------------------
__global__ void norms_k(const float* __restrict__ xq, const float* __restrict__ xkb,
                        float* __restrict__ qn, float* __restrict__ kn)
{
    const int row  = blockIdx.x;
    const int w    = threadIdx.x >> 5;
    const int lane = threadIdx.x & 31;
    const size_t base = (size_t)row * 1024 + (size_t)w * 256 + lane * 8;

    float4 a0 = *reinterpret_cast<const float4*>(xq + base);
    float4 a1 = *reinterpret_cast<const float4*>(xq + base + 4);
    float sq = a0.x*a0.x + a0.y*a0.y + a0.z*a0.z + a0.w*a0.w
             + a1.x*a1.x + a1.y*a1.y + a1.z*a1.z + a1.w*a1.w;
    float4 b0 = *reinterpret_cast<const float4*>(xkb + base);
    float4 b1 = *reinterpret_cast<const float4*>(xkb + base + 4);
    float sk = b0.x*b0.x + b0.y*b0.y + b0.z*b0.z + b0.w*b0.w
             + b1.x*b1.x + b1.y*b1.y + b1.z*b1.z + b1.w*b1.w;

    #pragma unroll
    for (int o = 16; o; o >>= 1) {
        sq += __shfl_xor_sync(0xFFFFFFFFu, sq, o);
        sk += __shfl_xor_sync(0xFFFFFFFFu, sk, o);
    }
    if (lane == 0) {
        qn[(size_t)row * 4 + w] = sq;
        kn[(size_t)row * 4 + w] = sk;
    }
}

// ---------------- softmax: read H f32, write P hi/lo bf16 --------------------
__global__ __launch_bounds__(256)
void softmax_k(const float* __restrict__ H, bf16* __restrict__ Ph, bf16* __restrict__ Pl)
{
    const int row = blockIdx.x;
    const float* p = H + (size_t)row * 2048;
    const int tid  = threadIdx.x;
    const int lane = tid & 31, warp = tid >> 5;

    float x[8];
    float4 v0 = *reinterpret_cast<const float4*>(p + tid * 8);
    float4 v1 = *reinterpret_cast<const float4*>(p + tid * 8 + 4);
    x[0]=v0.x; x[1]=v0.y; x[2]=v0.z; x[3]=v0.w;
    x[4]=v1.x; x[5]=v1.y; x[6]=v1.z; x[7]=v1.w;

    float m = x[0];
    #pragma unroll
    for (int i = 1; i < 8; i++) m = fmaxf(m, x[i]);
    #pragma unroll
    for (int o = 16; o; o >>= 1) m = fmaxf(m, __shfl_xor_sync(0xFFFFFFFFu, m, o));

    __shared__ float sm[8];
    __shared__ float ss[8];
    if (lane == 0) sm[warp] = m;
    __syncthreads();
    float M = sm[0];
    #pragma unroll
    for (int i = 1; i < 8; i++) M = fmaxf(M, sm[i]);

    float s = 0.f;
    #pragma unroll
    for (int i = 0; i < 8; i++) { x[i] = __expf(x[i] - M); s += x[i]; }
    #pragma unroll
    for (int o = 16; o; o >>= 1) s += __shfl_xor_sync(0xFFFFFFFFu, s, o);
    if (lane == 0) ss[warp] = s;
    __syncthreads();
    float S = 0.f;
    #pragma unroll
    for (int i = 0; i < 8; i++) S += ss[i];
    const float inv = 1.f / S;

    bf162* ph = reinterpret_cast<bf162*>(Ph + (size_t)row * 2048 + tid * 8);
    bf162* pl = reinterpret_cast<bf162*>(Pl + (size_t)row * 2048 + tid * 8);
    #pragma unroll
    for (int i = 0; i < 4; i++) {
        bf162 h, l;
        split2(x[2*i] * inv, x[2*i+1] * inv, h, l);
        ph[i] = h; pl[i] = l;
    }
}

// ---------------- launch ------------------------------------------------------
extern "C" void kernel_launch(void* const* d_in, const int* in_sizes, int n_in,
                              void* d_out, int out_size)
{
    const float* xsa    = (const float*)d_in[0];
    const float* Wq     = (const float*)d_in[1];
    const float* Wk     = (const float*)d_in[2];
    const float* Wv     = (const float*)d_in[3];
    const float* biasW  = (const float*)d_in[4];
    const float* bias2W = (const float*)d_in[5];
    float* out = (float*)d_out;

    float *p_xq, *p_xkb, *p_qn, *p_kn, *p_H;
    bf16 *xsa_h, *xsa_l, *wq_h, *wq_l, *wk_h, *wk_l, *wv_h, *wv_l;
    bf16 *xq_h, *xq_l, *xkb_h, *xkb_l, *P_h, *P_l, *vp_h, *vp_l;
    cudaGetSymbolAddress((void**)&p_xq,  g_xq);
    cudaGetSymbolAddress((void**)&p_xkb, g_xkb);
    cudaGetSymbolAddress((void**)&p_qn,  g_qn);
    cudaGetSymbolAddress((void**)&p_kn,  g_kn);
    cudaGetSymbolAddress((void**)&p_H,   g_H);
    cudaGetSymbolAddress((void**)&xsa_h, g_xsa_h);
    cudaGetSymbolAddress((void**)&xsa_l, g_xsa_l);
    cudaGetSymbolAddress((void**)&wq_h,  g_wq_h);
    cudaGetSymbolAddress((void**)&wq_l,  g_wq_l);
    cudaGetSymbolAddress((void**)&wk_h,  g_wk_h);
    cudaGetSymbolAddress((void**)&wk_l,  g_wk_l);
    cudaGetSymbolAddress((void**)&wv_h,  g_wv_h);
    cudaGetSymbolAddress((void**)&wv_l,  g_wv_l);
    cudaGetSymbolAddress((void**)&xq_h,  g_xq_h);
    cudaGetSymbolAddress((void**)&xq_l,  g_xq_l);
    cudaGetSymbolAddress((void**)&xkb_h, g_xkb_h);
    cudaGetSymbolAddress((void**)&xkb_l, g_xkb_l);
    cudaGetSymbolAddress((void**)&P_h,   g_P_h);
    cudaGetSymbolAddress((void**)&P_l,   g_P_l);
    cudaGetSymbolAddress((void**)&vp_h,  g_vp_h);
    cudaGetSymbolAddress((void**)&vp_l,  g_vp_l);

    cudaFuncSetAttribute(hgemm<0>, cudaFuncAttributeMaxDynamicSharedMemorySize, 98304);
    cudaFuncSetAttribute(hgemm<1>, cudaFuncAttributeMaxDynamicSharedMemorySize, 98304);
    cudaFuncSetAttribute(hgemm<2>, cudaFuncAttributeMaxDynamicSharedMemorySize, 98304);
    cudaFuncSetAttribute(hgemm<3>, cudaFuncAttributeMaxDynamicSharedMemorySize, 98304);
    cudaFuncSetAttribute(hgemm<4>, cudaFuncAttributeMaxDynamicSharedMemorySize, 98304);

    // input splits
    split_k<<<2048, 256>>>((const float4*)xsa, (bf162*)xsa_h, (bf162*)xsa_l, 524288);
    split_k<<<512,  256>>>((const float4*)Wq,  (bf162*)wq_h,  (bf162*)wq_l,  131072);
    split_k<<<512,  256>>>((const float4*)Wk,  (bf162*)wk_h,  (bf162*)wk_l,  131072);
    split_k<<<1024, 256>>>((const float4*)Wv,  (bf162*)wv_h,  (bf162*)wv_l,  262144);

    // S0: xq = xsa @ Wq^T  (f32 + hi/lo)
    hgemm<0><<<dim3(8, 32, 1), 256, 98304>>>(xsa_h, xsa_l, wq_h, wq_l,
                                             p_xq, xq_h, xq_l, nullptr, nullptr);
    // S1: xkb = xsa @ Wk^T + biasW
    hgemm<1><<<dim3(8, 32, 1), 256, 98304>>>(xsa_h, xsa_l, wk_h, wk_l,
                                             p_xkb, xkb_h, xkb_l, biasW, nullptr);
    // norms
    norms_k<<<4096, 128>>>(p_xq, p_xkb, p_qn, p_kn);
    // S2: H = (2*xq.xkb^T - qn - kn)/16
    hgemm<2><<<dim3(16, 16, 8), 256, 98304>>>(xq_h, xq_l, xkb_h, xkb_l,
                                              p_H, nullptr, nullptr, p_qn, p_kn);
    // softmax -> P hi/lo
    softmax_k<<<8 * 2048, 256>>>(p_H, P_h, P_l);
    // S3: Vp = xsa @ Wv3[k]  (hi/lo only)
    hgemm<3><<<dim3(4, 16, 8), 256, 98304>>>(xsa_h, xsa_l, wv_h, wv_l,
                                             nullptr, vp_h, vp_l, nullptr, nullptr);
    // S4: out = P @ Vp + bias2
    hgemm<4><<<dim3(4, 16, 8), 256, 98304>>>(P_h, P_l, vp_h, vp_l,
                                             out, nullptr, nullptr, bias2W, nullptr);
}